// round 14
// baseline (speedup 1.0000x reference)
#include <cuda_runtime.h>
#include <cstddef>

namespace {

constexpr int B = 8, T = 2048, H = 256, L = 16;
constexpr int S = 8;                    // t-strip per main work item
constexpr int WARPS = 4;                // warp g owns l in [4g, 4g+3]
constexpr int THREADS = WARPS * 32;     // 128
constexpr int STRIPS_PER_B = T / S;     // 256
constexpr int MAIN_ITEMS  = B * STRIPS_PER_B;              // 2048
constexpr int RELAY_T_PER_WARP = 16;
constexpr int RELAY_ITEMS = (B * T) / (WARPS * RELAY_T_PER_WARP);  // 256
constexpr int N_ITEMS = MAIN_ITEMS + RELAY_ITEMS;          // 2304
constexpr int GRID = 760;               // 5 blocks/SM persistent (152 SMs)

struct R8 { float v[8]; };
struct TrueT  { static constexpr bool value = true;  };
struct FalseT { static constexpr bool value = false; };

// Load 8 consecutive floats of row `row` (this lane's H-slice).
// CHK=true: zeros when row OOB (implements the reference's zero padding).
template <bool CHK>
__device__ __forceinline__ R8 load_row8(const float* __restrict__ base, int row, int hbase) {
  R8 r;
  if (!CHK || (unsigned)row < (unsigned)T) {
    const float4* p = reinterpret_cast<const float4*>(base + (size_t)row * H + hbase);
    float4 a = p[0];
    float4 b = p[1];
    r.v[0] = a.x; r.v[1] = a.y; r.v[2] = a.z; r.v[3] = a.w;
    r.v[4] = b.x; r.v[5] = b.y; r.v[6] = b.z; r.v[7] = b.w;
  } else {
#pragma unroll
    for (int j = 0; j < 8; j++) r.v[j] = 0.f;
  }
  return r;
}

// Interleaved merge: lanes with (lane&s)==0 carry the a-class partial sum,
// lanes with (lane&s)!=0 the b-class. One shfl per merge.
__device__ __forceinline__ float shfl_merge(float a, float b, int s, int lane) {
  const bool hi = (lane & s) != 0;
  float send = hi ? a : b;
  float recv = __shfl_xor_sync(0xffffffffu, send, s);
  return (hi ? b : a) + recv;
}

__global__ __launch_bounds__(THREADS, 5)
void ffm_kernel(const float* __restrict__ logits,
                const float* __restrict__ end_w,
                const float* __restrict__ whole_w,
                const float* __restrict__ relay_w,
                const float* __restrict__ relay_b,
                const float* __restrict__ length_bias,
                float* __restrict__ out,
                float* __restrict__ relay_out) {
  const int g    = threadIdx.x >> 5;
  const int lane = threadIdx.x & 31;
  const int hbase = lane * 8;
  // Writer lanes 0,16,8,24 hold finished sums for l = 4g + idx,
  // idx = bit16 + 2*bit8.
  const int  idx    = ((lane >> 4) & 1) + ((lane >> 3) & 1) * 2;
  const bool writer = (lane & 7) == 0;

  // Persistent grid-stride over work items: [0, MAIN_ITEMS) = main strips,
  // [MAIN_ITEMS, N_ITEMS) = relay chunks. All warps in a block take the
  // same branch; no smem, no syncs.
  for (int item = blockIdx.x; item < N_ITEMS; item += GRID) {
    if (item < MAIN_ITEMS) {
      // ---------------- main strip ----------------
      const int b  = item / STRIPS_PER_B;
      const int s0 = (item % STRIPS_PER_B) * S;
      const float* lb = logits + (size_t)b * T * H;

      // Weights in registers for this strip (L1-hot reload per item).
      float w0[8], w1[8], w2[8], w3[8], ew[8];
#pragma unroll
      for (int q = 0; q < 2; q++) {
        float4 x0 = *reinterpret_cast<const float4*>(whole_w + (4 * g + 0) * H + hbase + 4 * q);
        float4 x1 = *reinterpret_cast<const float4*>(whole_w + (4 * g + 1) * H + hbase + 4 * q);
        float4 x2 = *reinterpret_cast<const float4*>(whole_w + (4 * g + 2) * H + hbase + 4 * q);
        float4 x3 = *reinterpret_cast<const float4*>(whole_w + (4 * g + 3) * H + hbase + 4 * q);
        float4 xe = *reinterpret_cast<const float4*>(end_w + hbase + 4 * q);
        w0[4*q+0]=x0.x; w0[4*q+1]=x0.y; w0[4*q+2]=x0.z; w0[4*q+3]=x0.w;
        w1[4*q+0]=x1.x; w1[4*q+1]=x1.y; w1[4*q+2]=x1.z; w1[4*q+3]=x1.w;
        w2[4*q+0]=x2.x; w2[4*q+1]=x2.y; w2[4*q+2]=x2.z; w2[4*q+3]=x2.w;
        w3[4*q+0]=x3.x; w3[4*q+1]=x3.y; w3[4*q+2]=x3.z; w3[4*q+3]=x3.w;
        ew[4*q+0]=xe.x; ew[4*q+1]=xe.y; ew[4*q+2]=xe.z; ew[4*q+3]=xe.w;
      }
      const float bias = length_bias[4 * g + idx];

      auto body = [&](auto chk_tag) {
        constexpr bool CHK = decltype(chk_tag)::value;

        // 4-row register window. Row (s0 + u - 4g) loaded at step u into
        // slot u&3; at step u (p = u & 3), row r-4g-k lives in slot (p-k)&3.
        R8 Wn[4];
#pragma unroll
        for (int k = 1; k <= 3; k++)
          Wn[(4 - k) & 3] = load_row8<CHK>(lb, s0 - 4 * g - k, hbase);

#pragma unroll
        for (int u = 0; u < S; u++) {
          const int p = u & 3;
          const int r = s0 + u;

          Wn[p] = load_row8<CHK>(lb, r - 4 * g, hbase);  // advance window
          R8 cur;
          if (g == 0) cur = Wn[p];                       // warp 0: window row IS row r
          else        cur = load_row8<false>(lb, r, hbase);

          float e = 0.f, a0 = 0.f, a1 = 0.f, a2 = 0.f, a3 = 0.f;
#pragma unroll
          for (int j = 0; j < 8; j++) {
            const float c = cur.v[j];
            e  = fmaf(c, ew[j], e);
            a0 = fmaf(fmaxf(c, Wn[p].v[j]),           w0[j], a0);  // l = 4g
            a1 = fmaf(fmaxf(c, Wn[(p + 3) & 3].v[j]), w1[j], a1);  // l = 4g+1
            a2 = fmaf(fmaxf(c, Wn[(p + 2) & 3].v[j]), w2[j], a2);  // l = 4g+2
            a3 = fmaf(fmaxf(c, Wn[(p + 1) & 3].v[j]), w3[j], a3);  // l = 4g+3
          }
          // Fold end-score partial into each acc (lane-sum distributes).
          a0 += e; a1 += e; a2 += e; a3 += e;

          // Interleaved 4-value warp reduction: 5 shfl total.
          float x = shfl_merge(a0, a1, 16, lane);
          float y = shfl_merge(a2, a3, 16, lane);
          float z = shfl_merge(x,  y,  8,  lane);
          z += __shfl_xor_sync(0xffffffffu, z, 4);
          z += __shfl_xor_sync(0xffffffffu, z, 2);
          z += __shfl_xor_sync(0xffffffffu, z, 1);

          if (writer)
            out[(size_t)(b * T + r) * L + 4 * g + idx] = z + bias;
        }
      };

      // Min row touched is s0-15 (warp 3 prefill); max row s0+S-1 < T.
      if (s0 >= 16) body(FalseT{});
      else          body(TrueT{});
    } else {
      // ---------------- relay chunk ----------------
      // relay[b,t] = sum_h max(x[b,t,h], x_pad[b,t+L,h]) * relay_w[h] + relay_b
      const int c = item - MAIN_ITEMS;
      const int base_t = c * (WARPS * RELAY_T_PER_WARP) + g * RELAY_T_PER_WARP;
      const int b  = base_t / T;
      const int t0 = base_t % T;
      const float* lb = logits + (size_t)b * T * H;

      float rw[8];
#pragma unroll
      for (int q = 0; q < 2; q++) {
        float4 xr = *reinterpret_cast<const float4*>(relay_w + hbase + 4 * q);
        rw[4*q+0]=xr.x; rw[4*q+1]=xr.y; rw[4*q+2]=xr.z; rw[4*q+3]=xr.w;
      }
      const float rb = relay_b[0];

#pragma unroll
      for (int k = 0; k < RELAY_T_PER_WARP; k += 2) {
        const int t = t0 + k;
        R8 cur0 = load_row8<false>(lb, t, hbase);
        R8 cur1 = load_row8<false>(lb, t + 1, hbase);
        R8 nxt0 = load_row8<true>(lb, t + L, hbase);
        R8 nxt1 = load_row8<true>(lb, t + L + 1, hbase);

        float rel0 = 0.f, rel1 = 0.f;
#pragma unroll
        for (int j = 0; j < 8; j++) {
          rel0 = fmaf(fmaxf(cur0.v[j], nxt0.v[j]), rw[j], rel0);
          rel1 = fmaf(fmaxf(cur1.v[j], nxt1.v[j]), rw[j], rel1);
        }
        float m = shfl_merge(rel0, rel1, 16, lane);  // bit16: 0→t, 1→t+1
        m += __shfl_xor_sync(0xffffffffu, m, 8);
        m += __shfl_xor_sync(0xffffffffu, m, 4);
        m += __shfl_xor_sync(0xffffffffu, m, 2);
        m += __shfl_xor_sync(0xffffffffu, m, 1);
        if ((lane & 15) == 0)
          relay_out[(size_t)b * T + t + (lane >> 4)] = m + rb;
      }
    }
  }
}

}  // namespace

extern "C" void kernel_launch(void* const* d_in, const int* in_sizes, int n_in,
                              void* d_out, int out_size) {
  const float* logits  = (const float*)d_in[0];
  const float* end_w   = (const float*)d_in[1];
  const float* whole_w = (const float*)d_in[2];
  const float* relay_w = (const float*)d_in[3];
  const float* relay_b = (const float*)d_in[4];
  const float* lbias   = (const float*)d_in[5];

  float* out   = (float*)d_out;                // [B, T, L]
  float* relay = out + (size_t)B * T * L;      // [B, T] appended

  ffm_kernel<<<GRID, THREADS>>>(logits, end_w, whole_w, relay_w, relay_b,
                                lbias, out, relay);
}

// round 15
// speedup vs baseline: 1.1053x; 1.1053x over previous
#include <cuda_runtime.h>
#include <cstddef>

namespace {

constexpr int B = 8, T = 2048, H = 256, L = 16;
constexpr int S = 8;                    // t-strip per main work item
constexpr int WARPS = 4;                // warp g owns l in [4g, 4g+3]
constexpr int THREADS = WARPS * 32;     // 128
constexpr int STRIPS_PER_B = T / S;     // 256
constexpr int MAIN_ITEMS  = B * STRIPS_PER_B;              // 2048
constexpr int RELAY_T_PER_WARP = 16;
constexpr int RELAY_ITEMS = (B * T) / (WARPS * RELAY_T_PER_WARP);  // 256
constexpr int N_ITEMS = MAIN_ITEMS + RELAY_ITEMS;          // 2304 = 760*3 + 24
constexpr int GRID = 760;               // 5 blocks/SM x 152 SMs: one perfect wave

using u64 = unsigned long long;
struct P4 { u64 v[4]; };                // 8 floats as 4 packed f32x2
struct TrueT  { static constexpr bool value = true;  };
struct FalseT { static constexpr bool value = false; };

// ---- packed f32x2 helpers ----
__device__ __forceinline__ u64 fma2(u64 a, u64 b, u64 c) {
  u64 r;
  asm("fma.rn.f32x2 %0, %1, %2, %3;" : "=l"(r) : "l"(a), "l"(b), "l"(c));
  return r;
}
// Packed max on halves; mov.b64 pack/unpack are register-pair renames.
__device__ __forceinline__ u64 max2(u64 a, u64 b) {
  float alo, ahi, blo, bhi;
  asm("mov.b64 {%0, %1}, %2;" : "=f"(alo), "=f"(ahi) : "l"(a));
  asm("mov.b64 {%0, %1}, %2;" : "=f"(blo), "=f"(bhi) : "l"(b));
  float rlo = fmaxf(alo, blo);
  float rhi = fmaxf(ahi, bhi);
  u64 r;
  asm("mov.b64 %0, {%1, %2};" : "=l"(r) : "f"(rlo), "f"(rhi));
  return r;
}
__device__ __forceinline__ float collapse(u64 p) {  // lo + hi
  float lo, hi;
  asm("mov.b64 {%0, %1}, %2;" : "=f"(lo), "=f"(hi) : "l"(p));
  return lo + hi;
}

// Load 8 floats of row `row` (lane's H-slice) as 4 packed f32x2.
// CHK=true: zeros when row OOB (reference's zero padding).
template <bool CHK>
__device__ __forceinline__ P4 load_rowp(const float* __restrict__ base, int row, int hbase) {
  P4 r;
  if (!CHK || (unsigned)row < (unsigned)T) {
    const ulonglong2* p = reinterpret_cast<const ulonglong2*>(base + (size_t)row * H + hbase);
    ulonglong2 a = p[0];
    ulonglong2 b = p[1];
    r.v[0] = a.x; r.v[1] = a.y; r.v[2] = b.x; r.v[3] = b.y;
  } else {
    r.v[0] = r.v[1] = r.v[2] = r.v[3] = 0ull;   // == {0.f, 0.f}
  }
  return r;
}

// Interleaved merge: lanes with (lane&s)==0 carry the a-class partial sum,
// lanes with (lane&s)!=0 the b-class. One shfl per merge.
__device__ __forceinline__ float shfl_merge(float a, float b, int s, int lane) {
  const bool hi = (lane & s) != 0;
  float send = hi ? a : b;
  float recv = __shfl_xor_sync(0xffffffffu, send, s);
  return (hi ? b : a) + recv;
}

__global__ __launch_bounds__(THREADS, 5)
void ffm_kernel(const float* __restrict__ logits,
                const float* __restrict__ end_w,
                const float* __restrict__ whole_w,
                const float* __restrict__ relay_w,
                const float* __restrict__ relay_b,
                const float* __restrict__ length_bias,
                float* __restrict__ out,
                float* __restrict__ relay_out) {
  const int g    = threadIdx.x >> 5;
  const int lane = threadIdx.x & 31;
  const int hbase = lane * 8;
  // Writer lanes 0,16,8,24 hold finished sums for l = 4g + idx,
  // idx = bit16 + 2*bit8.
  const int  idx    = ((lane >> 4) & 1) + ((lane >> 3) & 1) * 2;
  const bool writer = (lane & 7) == 0;

  // Item-invariant state hoisted out of the persistent loop.
  P4 w0 = load_rowp<false>(whole_w + (4 * g + 0) * H, 0, hbase);
  P4 w1 = load_rowp<false>(whole_w + (4 * g + 1) * H, 0, hbase);
  P4 w2 = load_rowp<false>(whole_w + (4 * g + 2) * H, 0, hbase);
  P4 w3 = load_rowp<false>(whole_w + (4 * g + 3) * H, 0, hbase);
  P4 ew = load_rowp<false>(end_w, 0, hbase);
  const float bias = length_bias[4 * g + idx];

  // Persistent grid-stride over work items: [0, MAIN_ITEMS) = main strips,
  // [MAIN_ITEMS, N_ITEMS) = relay chunks. All warps in a block take the
  // same branch; no smem, no syncs.
  for (int item = blockIdx.x; item < N_ITEMS; item += GRID) {
    if (item < MAIN_ITEMS) {
      // ---------------- main strip ----------------
      const int b  = item >> 8;              // / STRIPS_PER_B
      const int s0 = (item & 255) << 3;      // % STRIPS_PER_B * S
      const float* lb = logits + (size_t)b * T * H;

      auto body = [&](auto chk_tag) {
        constexpr bool CHK = decltype(chk_tag)::value;

        // 4-row circular window. Row (s0 + u - 4g) loaded at step u into
        // slot u&3; at step u (p = u & 3), row r-4g-k lives in slot (p-k)&3.
        P4 Wn[4];
#pragma unroll
        for (int k = 1; k <= 3; k++)
          Wn[(4 - k) & 3] = load_rowp<CHK>(lb, s0 - 4 * g - k, hbase);

#pragma unroll
        for (int u = 0; u < S; u++) {
          const int p = u & 3;
          const int r = s0 + u;

          Wn[p] = load_rowp<CHK>(lb, r - 4 * g, hbase);  // advance window
          P4 cur;
          if (g == 0) cur = Wn[p];                       // warp 0: window row IS row r
          else        cur = load_rowp<false>(lb, r, hbase);

          u64 E = 0ull, A0 = 0ull, A1 = 0ull, A2 = 0ull, A3 = 0ull;
#pragma unroll
          for (int j = 0; j < 4; j++) {
            const u64 c = cur.v[j];
            E  = fma2(c, ew.v[j], E);
            A0 = fma2(max2(c, Wn[p].v[j]),           w0.v[j], A0);  // l = 4g
            A1 = fma2(max2(c, Wn[(p + 3) & 3].v[j]), w1.v[j], A1);  // l = 4g+1
            A2 = fma2(max2(c, Wn[(p + 2) & 3].v[j]), w2.v[j], A2);  // l = 4g+2
            A3 = fma2(max2(c, Wn[(p + 1) & 3].v[j]), w3.v[j], A3);  // l = 4g+3
          }
          // Collapse hi/lo halves and fold the end-score partial.
          const float e = collapse(E);
          float a0 = collapse(A0) + e;
          float a1 = collapse(A1) + e;
          float a2 = collapse(A2) + e;
          float a3 = collapse(A3) + e;

          // Interleaved 4-value warp reduction: 5 shfl total.
          float x = shfl_merge(a0, a1, 16, lane);
          float y = shfl_merge(a2, a3, 16, lane);
          float z = shfl_merge(x,  y,  8,  lane);
          z += __shfl_xor_sync(0xffffffffu, z, 4);
          z += __shfl_xor_sync(0xffffffffu, z, 2);
          z += __shfl_xor_sync(0xffffffffu, z, 1);

          if (writer)
            out[(size_t)(b * T + r) * L + 4 * g + idx] = z + bias;
        }
      };

      // Min row touched is s0-15 (warp 3 prefill); max row s0+S-1 < T.
      if (s0 >= 16) body(FalseT{});
      else          body(TrueT{});
    } else {
      // ---------------- relay chunk ----------------
      // relay[b,t] = sum_h max(x[b,t,h], x_pad[b,t+L,h]) * relay_w[h] + relay_b
      const int c = item - MAIN_ITEMS;
      const int base_t = c * (WARPS * RELAY_T_PER_WARP) + g * RELAY_T_PER_WARP;
      const int b  = base_t >> 11;           // / T
      const int t0 = base_t & 2047;          // % T
      const float* lb = logits + (size_t)b * T * H;

      // Relay weights reloaded per chunk (256 chunks; keeps them out of the
      // persistent register set).
      P4 rw = load_rowp<false>(relay_w, 0, hbase);
      const float rb = relay_b[0];

#pragma unroll
      for (int k = 0; k < RELAY_T_PER_WARP; k += 2) {
        const int t = t0 + k;
        P4 cur0 = load_rowp<false>(lb, t, hbase);
        P4 cur1 = load_rowp<false>(lb, t + 1, hbase);
        P4 nxt0 = load_rowp<true>(lb, t + L, hbase);
        P4 nxt1 = load_rowp<true>(lb, t + L + 1, hbase);

        u64 R0 = 0ull, R1 = 0ull;
#pragma unroll
        for (int j = 0; j < 4; j++) {
          R0 = fma2(max2(cur0.v[j], nxt0.v[j]), rw.v[j], R0);
          R1 = fma2(max2(cur1.v[j], nxt1.v[j]), rw.v[j], R1);
        }
        float rel0 = collapse(R0), rel1 = collapse(R1);

        float m = shfl_merge(rel0, rel1, 16, lane);  // bit16: 0→t, 1→t+1
        m += __shfl_xor_sync(0xffffffffu, m, 8);
        m += __shfl_xor_sync(0xffffffffu, m, 4);
        m += __shfl_xor_sync(0xffffffffu, m, 2);
        m += __shfl_xor_sync(0xffffffffu, m, 1);
        if ((lane & 15) == 0)
          relay_out[(size_t)b * T + t + (lane >> 4)] = m + rb;
      }
    }
  }
}

}  // namespace

extern "C" void kernel_launch(void* const* d_in, const int* in_sizes, int n_in,
                              void* d_out, int out_size) {
  const float* logits  = (const float*)d_in[0];
  const float* end_w   = (const float*)d_in[1];
  const float* whole_w = (const float*)d_in[2];
  const float* relay_w = (const float*)d_in[3];
  const float* relay_b = (const float*)d_in[4];
  const float* lbias   = (const float*)d_in[5];

  float* out   = (float*)d_out;                // [B, T, L]
  float* relay = out + (size_t)B * T * L;      // [B, T] appended

  ffm_kernel<<<GRID, THREADS>>>(logits, end_w, whole_w, relay_w, relay_b,
                                lbias, out, relay);
}